// round 7
// baseline (speedup 1.0000x reference)
#include <cuda_runtime.h>
#include <cuda_bf16.h>

#define U 64
#define M 8192
#define D 64
#define CHUNK 512
#define NCHUNK (M / CHUNK)   // 16
#define BLOCK 256
#define NWARP (BLOCK / 32)   // 8
#define SLOTS_PER_WARP (CHUNK / NWARP)   // 64

#define NEG_INF_F __int_as_float(0xff800000)

// Device scratch (no allocations allowed)
__device__ float  g_cmax[U * NCHUNK];
__device__ float  g_csum[U * NCHUNK];
__device__ float4 g_partial4[U * NCHUNK * (D / 4)];

// ---------------------------------------------------------------------------
// Kernel 1: scores + per-chunk softmax stats.
// grid (NCHUNK, U), block 256.
// Phase 1: dots. 16 lanes/slot (float4/lane); 4 slots per warp iteration with
//          2 independent LDG.128 per lane batched before the shfl chains
//          (MLP x2 vs previous round). Warp covers 1KB contiguous per iter.
// Phase 2: coalesced mask+temperature+score write + block stats.
// ---------------------------------------------------------------------------
__global__ void __launch_bounds__(BLOCK)
k_scores(const float* __restrict__ q,      // [U, D]
         const float* __restrict__ keys,   // [U, M, D]
         const int*   __restrict__ mask,   // [U, M] (0/1 int32)
         const float* __restrict__ tmpr,   // [U, 1]
         float* __restrict__ scores)       // [U, M]
{
    __shared__ float s_s[CHUNK];
    __shared__ float s_red[NWARP];

    const int u = blockIdx.y, c = blockIdx.x;
    const int tid = threadIdx.x, lane = tid & 31, warp = tid >> 5;
    const int sub = lane & 15, half = lane >> 4;
    const int m0 = c * CHUNK;

    const float4 q4 = ((const float4*)(q + u * D))[sub];

    // ---- Phase 1: raw dots into smem ----
    const int base_slot = warp * SLOTS_PER_WARP;
    #pragma unroll 4
    for (int i = 0; i < SLOTS_PER_WARP / 4; i++) {           // 16 iterations
        const int j0 = base_slot + 4 * i + half;             // slots j0, j0+2
        const size_t r0 = ((size_t)(u * M + m0 + j0))     * D;
        const size_t r1 = ((size_t)(u * M + m0 + j0 + 2)) * D;
        const float4 a = __ldcs((const float4*)(keys + r0) + sub);
        const float4 b = __ldcs((const float4*)(keys + r1) + sub);
        float p0 = a.x * q4.x + a.y * q4.y + a.z * q4.z + a.w * q4.w;
        float p1 = b.x * q4.x + b.y * q4.y + b.z * q4.z + b.w * q4.w;
        #pragma unroll
        for (int o = 1; o < 16; o <<= 1) {
            p0 += __shfl_xor_sync(0xffffffffu, p0, o);
            p1 += __shfl_xor_sync(0xffffffffu, p1, o);
        }
        if (sub == 0) {
            s_s[j0]     = p0;
            s_s[j0 + 2] = p1;
        }
    }
    __syncthreads();

    // ---- Phase 2: mask + temperature, coalesced global write, stats ----
    const float t = tmpr[u];
    const int j2 = tid * 2;
    const float2 sv = *(const float2*)&s_s[j2];
    const int2  mk = ((const int2*)(mask + u * M + m0))[tid];
    float s0 = (mk.x != 0) ? -1e9f : sv.x;
    float s1 = (mk.y != 0) ? -1e9f : sv.y;
    s0 = s0 / t;
    s1 = s1 / t;
    // default (write-back) store: scores are re-read by k_out and fit in L2
    ((float2*)(scores + (size_t)u * M + m0))[tid] = make_float2(s0, s1);

    // block max
    float lm = fmaxf(s0, s1);
    #pragma unroll
    for (int o = 16; o > 0; o >>= 1) lm = fmaxf(lm, __shfl_xor_sync(0xffffffffu, lm, o));
    if (lane == 0) s_red[warp] = lm;
    __syncthreads();
    float cmax = s_red[0];
    #pragma unroll
    for (int w = 1; w < NWARP; w++) cmax = fmaxf(cmax, s_red[w]);
    __syncthreads();   // protect s_red reuse

    // block sum of exp(s - cmax)
    float ls = __expf(s0 - cmax) + __expf(s1 - cmax);
    #pragma unroll
    for (int o = 16; o > 0; o >>= 1) ls += __shfl_xor_sync(0xffffffffu, ls, o);
    if (lane == 0) s_red[warp] = ls;
    __syncthreads();
    if (tid == 0) {
        float sm = 0.0f;
        #pragma unroll
        for (int w = 0; w < NWARP; w++) sm += s_red[w];
        g_cmax[u * NCHUNK + c] = cmax;
        g_csum[u * NCHUNK + c] = sm;
    }
}

// ---------------------------------------------------------------------------
// Kernel 2: recombine -> weights (coalesced, via smem), weighted memory sum
// into deterministic per-chunk partials + fused memories copy.
// 4 slots per warp iteration, 2 independent load/store streams.
// grid (NCHUNK, U), block 256.
// ---------------------------------------------------------------------------
__global__ void __launch_bounds__(BLOCK)
k_out(const float* __restrict__ mem,       // [U, M, D]
      float* __restrict__ weights,         // [U, M] (scores on entry)
      float* __restrict__ memout)          // [U, M, D]
{
    __shared__ float  s_w[CHUNK];
    __shared__ float4 s_acc[NWARP][32];

    const int u = blockIdx.y, c = blockIdx.x;
    const int tid = threadIdx.x, lane = tid & 31, warp = tid >> 5;
    const int sub = lane & 15, half = lane >> 4;
    const int m0 = c * CHUNK;

    // ---- global softmax stats (flash recombine, broadcast loads) ----
    float gmax = NEG_INF_F;
    #pragma unroll
    for (int j = 0; j < NCHUNK; j++) gmax = fmaxf(gmax, g_cmax[u * NCHUNK + j]);
    float gsum = 0.0f;
    #pragma unroll
    for (int j = 0; j < NCHUNK; j++)
        gsum += g_csum[u * NCHUNK + j] * __expf(g_cmax[u * NCHUNK + j] - gmax);
    const float inv = 1.0f / gsum;

    // ---- Phase 1: all chunk weights, coalesced (likely L2 hits on scores) ----
    const int j2 = tid * 2;
    const float2 sv = ((const float2*)(weights + (size_t)u * M + m0))[tid];
    const float w0 = __expf(sv.x - gmax) * inv;
    const float w1 = __expf(sv.y - gmax) * inv;
    s_w[j2]     = w0;
    s_w[j2 + 1] = w1;
    __stcs((float2*)(weights + (size_t)u * M + m0) + tid, make_float2(w0, w1));
    __syncthreads();

    // ---- Phase 2: stream memories once: weighted sum + fused copy ----
    float4 acc0 = make_float4(0.0f, 0.0f, 0.0f, 0.0f);
    float4 acc1 = make_float4(0.0f, 0.0f, 0.0f, 0.0f);
    const int base_slot = warp * SLOTS_PER_WARP;
    #pragma unroll 4
    for (int i = 0; i < SLOTS_PER_WARP / 4; i++) {
        const int j0 = base_slot + 4 * i + half;
        const size_t r0 = ((size_t)(u * M + m0 + j0))     * D;
        const size_t r1 = ((size_t)(u * M + m0 + j0 + 2)) * D;
        const float4 a = __ldcs((const float4*)(mem + r0) + sub);
        const float4 b = __ldcs((const float4*)(mem + r1) + sub);
        const float wa = s_w[j0];
        const float wb = s_w[j0 + 2];
        acc0.x = fmaf(wa, a.x, acc0.x);
        acc0.y = fmaf(wa, a.y, acc0.y);
        acc0.z = fmaf(wa, a.z, acc0.z);
        acc0.w = fmaf(wa, a.w, acc0.w);
        acc1.x = fmaf(wb, b.x, acc1.x);
        acc1.y = fmaf(wb, b.y, acc1.y);
        acc1.z = fmaf(wb, b.z, acc1.z);
        acc1.w = fmaf(wb, b.w, acc1.w);
        __stcs((float4*)(memout + r0) + sub, a);             // fused copy
        __stcs((float4*)(memout + r1) + sub, b);
    }
    acc0.x += acc1.x; acc0.y += acc1.y; acc0.z += acc1.z; acc0.w += acc1.w;
    s_acc[warp][lane] = acc0;
    __syncthreads();

    // ---- Phase 3: reduce 16 partial vectors (8 warps x 2 halves) ----
    if (tid < 16) {
        float4 tsum = make_float4(0.0f, 0.0f, 0.0f, 0.0f);
        #pragma unroll
        for (int w = 0; w < NWARP; w++) {
            #pragma unroll
            for (int h = 0; h < 2; h++) {
                const float4 v = s_acc[w][h * 16 + tid];
                tsum.x += v.x; tsum.y += v.y; tsum.z += v.z; tsum.w += v.w;
            }
        }
        g_partial4[(u * NCHUNK + c) * (D / 4) + tid] = tsum;
    }
}

// ---------------------------------------------------------------------------
// Kernel 3: reduce chunk partials -> outputs. grid U, block D. Deterministic.
// ---------------------------------------------------------------------------
__global__ void k_red(float* __restrict__ outp)               // [U, D]
{
    const int u = blockIdx.x, d = threadIdx.x;
    const float* gp = (const float*)g_partial4;
    float s = 0.0f;
    #pragma unroll
    for (int c = 0; c < NCHUNK; c++) s += gp[(u * NCHUNK + c) * D + d];
    outp[u * D + d] = s;
}

extern "C" void kernel_launch(void* const* d_in, const int* in_sizes, int n_in,
                              void* d_out, int out_size)
{
    const float* attention  = (const float*)d_in[0];  // [U, D]
    const float* attentions = (const float*)d_in[1];  // [U, M, D]
    const float* memories   = (const float*)d_in[2];  // [U, M, D]
    const float* tmpr       = (const float*)d_in[3];  // [U, 1]
    const int*   mask       = (const int*)  d_in[4];  // [U, M]

    float* out          = (float*)d_out;
    float* out_outputs  = out;                        // [U, D]
    float* out_weights  = out + U * D;                // [U, M]
    float* out_memories = out + U * D + U * M;        // [U, M, D]

    dim3 grid(NCHUNK, U);
    k_scores<<<grid, BLOCK>>>(attention, attentions, mask, tmpr, out_weights);
    k_out<<<grid, BLOCK>>>(memories, out_weights, out_memories);
    k_red<<<U, D>>>(out_outputs);
}